// round 14
// baseline (speedup 1.0000x reference)
#include <cuda_runtime.h>
#include <cuda_bf16.h>

#define B_   32
#define N_   4096
#define D_   64
#define BC_  4
#define C_   129
#define NSL_ 8                 // slices per cluster-batch
#define SL_  (N_ / NSL_)       // 512 labels per slice
#define NT_  9                 // q tiles of 16
#define NCH_ 3                 // member-broadcast chunks per tile

// Scratch (no allocations allowed)
__device__ __align__(16) int g_lab[BC_ * N_];
__device__ __align__(16) int g_parthist[BC_ * NSL_ * C_];
__device__ __align__(16) int g_order[BC_ * N_];
__device__ __align__(16) int g_starts[BC_ * (C_ + 1)];
__device__ __align__(16) float g_Qc[B_ * C_ * D_];
__device__ __align__(16) float g_Kc[B_ * C_ * D_];
__device__ __align__(16) float g_Vc[B_ * C_ * D_];
__device__ __align__(16) float g_P[B_ * NT_ * 16 * 132];   // softmaxed probs

// ---------------------------------------------------------------------------
// Kernel 1a: decode labels + per-slice histogram. grid (NSL_, BC_) x 256.
// ---------------------------------------------------------------------------
__global__ void __launch_bounds__(256)
hist_kernel(const void* __restrict__ cl_raw) {
    __shared__ int hist[C_];
    __shared__ int s_bad;
    int blk = blockIdx.x;
    int bc  = blockIdx.y;
    int t   = threadIdx.x;

    if (t < 32) {
        long long v = __ldg((const long long*)cl_raw + t);
        unsigned bad = __ballot_sync(0xFFFFFFFFu, v < 0 || v >= C_);
        if (t == 0) s_bad = (bad != 0);
    }
    if (t < C_) hist[t] = 0;
    __syncthreads();

    int base = bc * N_ + blk * SL_;
    int lab[2];
    if (s_bad) {
        const int* c32 = (const int*)cl_raw;
        lab[0] = c32[base + t];
        lab[1] = c32[base + t + 256];
    } else {
        const long long* c64 = (const long long*)cl_raw;
        lab[0] = (int)c64[base + t];
        lab[1] = (int)c64[base + t + 256];
    }
    g_lab[base + t]       = lab[0];
    g_lab[base + t + 256] = lab[1];
    atomicAdd(&hist[lab[0]], 1);
    atomicAdd(&hist[lab[1]], 1);
    __syncthreads();

    if (t < C_) g_parthist[(bc * NSL_ + blk) * C_ + t] = hist[t];
}

// ---------------------------------------------------------------------------
// Kernel 1b: combine partial hists, scan, scatter own slice.
// grid (NSL_, BC_) x 256.
// ---------------------------------------------------------------------------
__global__ void __launch_bounds__(256)
scatter_kernel() {
    __shared__ int sTot[C_];
    __shared__ int sPre[C_];
    __shared__ int sStart[C_];
    __shared__ int offs[C_];
    int blk = blockIdx.x;
    int bc  = blockIdx.y;
    int t   = threadIdx.x;

    if (t < C_) {
        const int* ph = g_parthist + bc * NSL_ * C_ + t;
        int pre = 0, tot = 0;
#pragma unroll
        for (int s = 0; s < NSL_; s++) {
            int v = __ldg(ph + s * C_);
            if (s < blk) pre += v;
            tot += v;
        }
        sPre[t] = pre;
        sTot[t] = tot;
    }
    __syncthreads();

    if (t < 32) {
        int base = t * 5;
        int v[5], s = 0;
#pragma unroll
        for (int i = 0; i < 5; i++) {
            int c = base + i;
            v[i] = (c < C_) ? sTot[c] : 0;
            s += v[i];
        }
        int run = s;
#pragma unroll
        for (int o = 1; o < 32; o <<= 1) {
            int x = __shfl_up_sync(0xFFFFFFFFu, run, o);
            if (t >= o) run += x;
        }
        int acc = run - s;
#pragma unroll
        for (int i = 0; i < 5; i++) {
            int c = base + i;
            if (c < C_) {
                sStart[c] = acc;
                if (blk == 0) g_starts[bc * (C_ + 1) + c] = acc;
            }
            acc += v[i];
        }
        if (t == 31 && blk == 0) g_starts[bc * (C_ + 1) + C_] = N_;
    }
    __syncthreads();

    if (t < C_) offs[t] = sStart[t] + sPre[t];
    __syncthreads();

    int base = bc * N_ + blk * SL_;
#pragma unroll
    for (int r = 0; r < 2; r++) {
        int i = r * 256 + t;
        int lab = g_lab[base + i];
        int p = atomicAdd(&offs[lab], 1);
        g_order[bc * N_ + p] = blk * SL_ + i;
    }
}

// ---------------------------------------------------------------------------
// Kernel 2: per-cluster centers. Warp owns a cluster; 8-member batches,
// ord prefetched one batch ahead. grid (32,16) x 256, 3 blocks/SM.
// ---------------------------------------------------------------------------
__global__ void __launch_bounds__(256, 3)
centers_kernel(const float* __restrict__ Q,
               const float* __restrict__ K,
               const float* __restrict__ V) {
    int b    = blockIdx.x;
    int bc   = b & 3;
    int wid  = threadIdx.x >> 5;
    int lane = threadIdx.x & 31;
    int half = lane >> 4;
    int dc   = lane & 15;

    const float4* Qb = (const float4*)(Q + (size_t)b * N_ * D_);
    const float4* Kb = (const float4*)(K + (size_t)b * N_ * D_);
    const float4* Vb = (const float4*)(V + (size_t)b * N_ * D_);
    const int* ord = g_order + bc * N_;
    const int* sts = g_starts + bc * (C_ + 1);

    for (int c = blockIdx.y * 8 + wid; c < C_; c += 128) {
        int s0 = sts[c], s1 = sts[c + 1];
        float w = (s1 > s0) ? 1.0f / (float)(s1 - s0) : 0.0f;
        float4 aq = {0.f,0.f,0.f,0.f}, ak = aq, av = aq;

        int   nn[4];
        float mk[4];
#pragma unroll
        for (int p = 0; p < 4; p++) {
            int mm = s0 + 2 * p + half;
            bool vld = mm < s1;
            nn[p] = __ldg(ord + (vld ? mm : 0));
            mk[p] = vld ? 1.0f : 0.0f;
        }
        for (int m = s0; m < s1; m += 8) {
            int   nn2[4];
            float mk2[4];
#pragma unroll
            for (int p = 0; p < 4; p++) {
                int mm = m + 8 + 2 * p + half;
                bool vld = mm < s1;
                nn2[p] = __ldg(ord + (vld ? mm : 0));
                mk2[p] = vld ? 1.0f : 0.0f;
            }
            float4 q4[4], k4[4], v4[4];
#pragma unroll
            for (int p = 0; p < 4; p++) {
                size_t off = (size_t)nn[p] * 16 + dc;
                q4[p] = Qb[off];
                k4[p] = Kb[off];
                v4[p] = Vb[off];
            }
#pragma unroll
            for (int p = 0; p < 4; p++) {
                aq.x = fmaf(mk[p], q4[p].x, aq.x); aq.y = fmaf(mk[p], q4[p].y, aq.y);
                aq.z = fmaf(mk[p], q4[p].z, aq.z); aq.w = fmaf(mk[p], q4[p].w, aq.w);
                ak.x = fmaf(mk[p], k4[p].x, ak.x); ak.y = fmaf(mk[p], k4[p].y, ak.y);
                ak.z = fmaf(mk[p], k4[p].z, ak.z); ak.w = fmaf(mk[p], k4[p].w, ak.w);
                av.x = fmaf(mk[p], v4[p].x, av.x); av.y = fmaf(mk[p], v4[p].y, av.y);
                av.z = fmaf(mk[p], v4[p].z, av.z); av.w = fmaf(mk[p], v4[p].w, av.w);
            }
#pragma unroll
            for (int p = 0; p < 4; p++) { nn[p] = nn2[p]; mk[p] = mk2[p]; }
        }
        unsigned fm = 0xFFFFFFFFu;
        aq.x += __shfl_xor_sync(fm, aq.x, 16); aq.y += __shfl_xor_sync(fm, aq.y, 16);
        aq.z += __shfl_xor_sync(fm, aq.z, 16); aq.w += __shfl_xor_sync(fm, aq.w, 16);
        ak.x += __shfl_xor_sync(fm, ak.x, 16); ak.y += __shfl_xor_sync(fm, ak.y, 16);
        ak.z += __shfl_xor_sync(fm, ak.z, 16); ak.w += __shfl_xor_sync(fm, ak.w, 16);
        av.x += __shfl_xor_sync(fm, av.x, 16); av.y += __shfl_xor_sync(fm, av.y, 16);
        av.z += __shfl_xor_sync(fm, av.z, 16); av.w += __shfl_xor_sync(fm, av.w, 16);
        if (half == 0) {
            size_t o = (size_t)(b * C_ + c) * 16 + dc;
            ((float4*)g_Qc)[o] = make_float4(aq.x*w, aq.y*w, aq.z*w, aq.w*w);
            ((float4*)g_Kc)[o] = make_float4(ak.x*w, ak.y*w, ak.z*w, ak.w*w);
            ((float4*)g_Vc)[o] = make_float4(av.x*w, av.y*w, av.z*w, av.w*w);
        }
    }
}

// ---------------------------------------------------------------------------
// Kernel 3a: scores + softmax -> g_P. grid (32, 9) x 256, 3 blocks/SM.
// SMEM (floats): sK[C*68] | sQt[16*68] | sP[16*132] | sCnt[132]  ~48.4KB
// ---------------------------------------------------------------------------
#define SC_SMEM_FLOATS (C_*68 + 16*68 + 16*132 + 132)
#define SC_SMEM_BYTES  (SC_SMEM_FLOATS * 4)

__global__ void __launch_bounds__(256, 3)
scores_kernel(float* __restrict__ attn_out) {
    extern __shared__ __align__(16) float smem[];
    float* sK   = smem;                    // stride 68 (17 f4)
    float* sQt  = sK + C_ * 68;            // stride 68
    float* sP   = sQt + 16 * 68;           // 16 x 132
    float* sCnt = sP + 16 * 132;

    int b  = blockIdx.x;
    int bc = b & 3;
    int q0 = blockIdx.y * 16;
    int t  = threadIdx.x;

    const int* sts = g_starts + bc * (C_ + 1);
    for (int k = t; k < C_; k += 256) sCnt[k] = (float)(sts[k + 1] - sts[k]);

    float4* sK4 = (float4*)sK;
    float4* sQ4 = (float4*)sQt;
    const float4* Kc4 = (const float4*)(g_Kc + (size_t)b * C_ * D_);
    const float4* Qc4 = (const float4*)(g_Qc + (size_t)b * C_ * D_);
    for (int i = t; i < C_ * 16; i += 256) {
        int k = i >> 4, d4 = i & 15;
        sK4[k * 17 + d4] = Kc4[i];
    }
    {
        int j = t >> 4, d4 = t & 15, q = q0 + j;
        sQ4[j * 17 + d4] = (q < C_) ? Qc4[q * 16 + d4] : make_float4(0,0,0,0);
    }
    __syncthreads();

    // ---- Phase A: scores. thread = (q-quad jp4, k-slot). 4-way q blocking.
    {
        int w      = t >> 5;
        int jp4    = w >> 1;
        int kstart = (t & 31) + 32 * (w & 1);
        float4 a0[4], a1[4];
#pragma unroll
        for (int qi = 0; qi < 4; qi++) { a0[qi] = make_float4(0,0,0,0); a1[qi] = a0[qi]; }
#pragma unroll 4
        for (int d4 = 0; d4 < 16; d4++) {
            float4 kva = sK4[kstart * 17 + d4];
            float4 kvb = sK4[(kstart + 64) * 17 + d4];
#pragma unroll
            for (int qi = 0; qi < 4; qi++) {
                float4 qv = sQ4[(4 * jp4 + qi) * 17 + d4];
                a0[qi].x = fmaf(qv.x, kva.x, a0[qi].x); a0[qi].y = fmaf(qv.y, kva.y, a0[qi].y);
                a0[qi].z = fmaf(qv.z, kva.z, a0[qi].z); a0[qi].w = fmaf(qv.w, kva.w, a0[qi].w);
                a1[qi].x = fmaf(qv.x, kvb.x, a1[qi].x); a1[qi].y = fmaf(qv.y, kvb.y, a1[qi].y);
                a1[qi].z = fmaf(qv.z, kvb.z, a1[qi].z); a1[qi].w = fmaf(qv.w, kvb.w, a1[qi].w);
            }
        }
#pragma unroll
        for (int qi = 0; qi < 4; qi++) {
            sP[(4 * jp4 + qi) * 132 + kstart]      = (a0[qi].x + a0[qi].y) + (a0[qi].z + a0[qi].w);
            sP[(4 * jp4 + qi) * 132 + kstart + 64] = (a1[qi].x + a1[qi].y) + (a1[qi].z + a1[qi].w);
        }
        if (kstart == 0) {   // epilogue column k=128
            float4 a4[4];
#pragma unroll
            for (int qi = 0; qi < 4; qi++) a4[qi] = make_float4(0,0,0,0);
#pragma unroll 4
            for (int d4 = 0; d4 < 16; d4++) {
                float4 kv = sK4[128 * 17 + d4];
#pragma unroll
                for (int qi = 0; qi < 4; qi++) {
                    float4 qv = sQ4[(4 * jp4 + qi) * 17 + d4];
                    a4[qi].x = fmaf(qv.x, kv.x, a4[qi].x); a4[qi].y = fmaf(qv.y, kv.y, a4[qi].y);
                    a4[qi].z = fmaf(qv.z, kv.z, a4[qi].z); a4[qi].w = fmaf(qv.w, kv.w, a4[qi].w);
                }
            }
#pragma unroll
            for (int qi = 0; qi < 4; qi++)
                sP[(4 * jp4 + qi) * 132 + 128] = (a4[qi].x + a4[qi].y) + (a4[qi].z + a4[qi].w);
        }
    }
    __syncthreads();

    // ---- Softmax with count reweighting: one warp per q row.
    {
        int wid = t >> 5, lane = t & 31;
        for (int j = wid; j < 16; j += 8) {
            float* row = &sP[j * 132];
            float v[5];
            float mx = -1e30f;
#pragma unroll
            for (int i = 0; i < 5; i++) {
                int k = lane + 32 * i;
                v[i] = (k < C_) ? row[k] : -1e30f;
                mx = fmaxf(mx, v[i]);
            }
#pragma unroll
            for (int o = 16; o; o >>= 1) mx = fmaxf(mx, __shfl_xor_sync(0xFFFFFFFFu, mx, o));
            float e[5];
            float sum = 0.f;
#pragma unroll
            for (int i = 0; i < 5; i++) {
                int k = lane + 32 * i;
                e[i] = (k < C_) ? __expf(v[i] - mx) * sCnt[k] : 0.0f;
                sum += e[i];
            }
#pragma unroll
            for (int o = 16; o; o >>= 1) sum += __shfl_xor_sync(0xFFFFFFFFu, sum, o);
            float inv = 1.0f / sum;
#pragma unroll
            for (int i = 0; i < 5; i++) {
                int k = lane + 32 * i;
                if (k < 132) row[k] = (k < C_) ? e[i] * inv : 0.0f;   // zero-pad 129..131
            }
            if (lane == 0 && (q0 + j) < C_) attn_out[b * C_ + q0 + j] = e[0] * inv;
        }
    }
    __syncthreads();

    // ---- Write P tile to global (float4, contiguous 16x132 block)
    {
        float4* gP4 = (float4*)(g_P + (size_t)(b * NT_ + blockIdx.y) * 16 * 132);
        const float4* sP4 = (const float4*)sP;
        for (int i = t; i < 16 * 33; i += 256) gP4[i] = sP4[i];
    }
}

// ---------------------------------------------------------------------------
// Kernel 3b: out = P @ Vc, broadcast to members. grid (32, 9, NCH_) x 256.
// Each z-chunk redundantly computes the tiny GEMM, then broadcasts its 1/NCH_
// share of each cluster's member list (3x store-issue parallelism).
// SMEM (floats): sV[C*64] | sP[16*132] | sOut[16*64] | (ints) sOrd[1024]|sSt[17]
// ---------------------------------------------------------------------------
#define AP_SMEM_FLOATS (C_*64 + 16*132 + 16*64)
#define AP_SMEM_BYTES  ((AP_SMEM_FLOATS + 1024 + 17 + 3) * 4)

__global__ void __launch_bounds__(256, 3)
apply_kernel(float* __restrict__ out) {
    extern __shared__ __align__(16) float smem[];
    float* sV   = smem;                    // stride 64 (16 f4)
    float* sP   = sV + C_ * 64;            // 16 x 132
    float* sOut = sP + 16 * 132;           // 16 x 64
    int*   sOrd = (int*)(sOut + 16 * 64);  // 1024
    int*   sSt  = sOrd + 1024;             // 17

    int b  = blockIdx.x;
    int bc = b & 3;
    int q0 = blockIdx.y * 16;
    int ch = blockIdx.z;
    int t  = threadIdx.x;

    const int* sts = g_starts + bc * (C_ + 1);
    const int* ord = g_order + bc * N_;
    int qe = (q0 + 16 < C_) ? q0 + 16 : C_;
    if (t <= qe - q0) sSt[t] = sts[q0 + t];

    float4* sV4 = (float4*)sV;
    const float4* Vc4 = (const float4*)(g_Vc + (size_t)b * C_ * D_);
    for (int i = t; i < C_ * 16; i += 256) sV4[i] = Vc4[i];
    {
        float4* sP4 = (float4*)sP;
        const float4* gP4 = (const float4*)(g_P + (size_t)(b * NT_ + blockIdx.y) * 16 * 132);
        for (int i = t; i < 16 * 33; i += 256) sP4[i] = gP4[i];
    }
    int m0 = sts[q0];
    int mcount = sts[qe] - m0;
    bool fit = (mcount <= 1024);
    if (fit) for (int i = t; i < mcount; i += 256) sOrd[i] = __ldg(ord + m0 + i);
    __syncthreads();

    // ---- out[j][dv] = sum_k P[j][k] * V[k][dv]; thread owns (j, dv) fully.
    {
        int j  = t >> 4;
        int dv = t & 15;
        const float* pr = &sP[j * 132];
        float4 acc = make_float4(0, 0, 0, 0);
#pragma unroll 4
        for (int k = 0; k < C_; k++) {
            float4 v = sV4[k * 16 + dv];
            float  p = pr[k];
            acc.x = fmaf(p, v.x, acc.x); acc.y = fmaf(p, v.y, acc.y);
            acc.z = fmaf(p, v.z, acc.z); acc.w = fmaf(p, v.w, acc.w);
        }
        ((float4*)sOut)[j * 16 + dv] = acc;
    }
    __syncthreads();

    // ---- Broadcast: this chunk covers member slots rowSlot + ch*16 (step 48)
    {
        float4* sOut4 = (float4*)sOut;
        int rowSlot = (t >> 4) + ch * 16;
        int dv = t & 15;
        int nj = qe - q0;
        if (fit) {
            for (int j = 0; j < nj; j++) {
                int s0l = sSt[j] - m0, cnt = sSt[j + 1] - sSt[j];
                float4 val = sOut4[j * 16 + dv];
                for (int m = rowSlot; m < cnt; m += 16 * NCH_) {
                    int n = sOrd[s0l + m];
                    ((float4*)(out + ((size_t)b * N_ + n) * D_))[dv] = val;
                }
            }
        } else {
            for (int j = 0; j < nj; j++) {
                int s0g = sSt[j], cnt = sSt[j + 1] - s0g;
                float4 val = sOut4[j * 16 + dv];
                for (int m = rowSlot; m < cnt; m += 16 * NCH_) {
                    int n = __ldg(ord + s0g + m);
                    ((float4*)(out + ((size_t)b * N_ + n) * D_))[dv] = val;
                }
            }
        }
    }
}

// ---------------------------------------------------------------------------
extern "C" void kernel_launch(void* const* d_in, const int* in_sizes, int n_in,
                              void* d_out, int out_size) {
    const float* Q  = (const float*)d_in[0];
    const float* K  = (const float*)d_in[1];
    const float* V  = (const float*)d_in[2];
    const void*  cl = d_in[3];
    float* out = (float*)d_out;
    float* attn_out = out + (size_t)B_ * N_ * D_;

    cudaFuncSetAttribute(scores_kernel, cudaFuncAttributeMaxDynamicSharedMemorySize,
                         SC_SMEM_BYTES);
    cudaFuncSetAttribute(apply_kernel, cudaFuncAttributeMaxDynamicSharedMemorySize,
                         AP_SMEM_BYTES);

    hist_kernel<<<dim3(NSL_, BC_), 256>>>(cl);
    scatter_kernel<<<dim3(NSL_, BC_), 256>>>();
    centers_kernel<<<dim3(B_, 16), 256>>>(Q, K, V);
    scores_kernel<<<dim3(B_, NT_), 256, SC_SMEM_BYTES>>>(attn_out);
    apply_kernel<<<dim3(B_, NT_, NCH_), 256, AP_SMEM_BYTES>>>(out);
}

// round 15
// speedup vs baseline: 1.1984x; 1.1984x over previous
#include <cuda_runtime.h>
#include <cuda_bf16.h>

#define B_   32
#define N_   4096
#define D_   64
#define BC_  4
#define C_   129
#define NSL_ 8                 // slices per cluster-batch
#define SL_  (N_ / NSL_)       // 512 labels per slice
#define NT_  9                 // q tiles of 16

// Scratch (no allocations allowed)
__device__ __align__(16) int g_lab[BC_ * N_];
__device__ __align__(16) int g_parthist[BC_ * NSL_ * C_];
__device__ __align__(16) int g_order[BC_ * N_];
__device__ __align__(16) int g_starts[BC_ * (C_ + 1)];
__device__ __align__(16) float g_Qc[B_ * C_ * D_];
__device__ __align__(16) float g_Kc[B_ * C_ * D_];
__device__ __align__(16) float g_Vc[B_ * C_ * D_];
__device__ __align__(16) float g_P[B_ * NT_ * 16 * 132];   // softmaxed probs
__device__ __align__(16) float g_Vout[B_ * C_ * D_];       // attended centers

// ---------------------------------------------------------------------------
// Kernel 1a: decode labels + per-slice histogram. grid (NSL_, BC_) x 256.
// ---------------------------------------------------------------------------
__global__ void __launch_bounds__(256)
hist_kernel(const void* __restrict__ cl_raw) {
    __shared__ int hist[C_];
    __shared__ int s_bad;
    int blk = blockIdx.x;
    int bc  = blockIdx.y;
    int t   = threadIdx.x;

    if (t < 32) {
        long long v = __ldg((const long long*)cl_raw + t);
        unsigned bad = __ballot_sync(0xFFFFFFFFu, v < 0 || v >= C_);
        if (t == 0) s_bad = (bad != 0);
    }
    if (t < C_) hist[t] = 0;
    __syncthreads();

    int base = bc * N_ + blk * SL_;
    int lab[2];
    if (s_bad) {
        const int* c32 = (const int*)cl_raw;
        lab[0] = c32[base + t];
        lab[1] = c32[base + t + 256];
    } else {
        const long long* c64 = (const long long*)cl_raw;
        lab[0] = (int)c64[base + t];
        lab[1] = (int)c64[base + t + 256];
    }
    g_lab[base + t]       = lab[0];
    g_lab[base + t + 256] = lab[1];
    atomicAdd(&hist[lab[0]], 1);
    atomicAdd(&hist[lab[1]], 1);
    __syncthreads();

    if (t < C_) g_parthist[(bc * NSL_ + blk) * C_ + t] = hist[t];
}

// ---------------------------------------------------------------------------
// Kernel 1b: combine partial hists, scan, scatter own slice.
// grid (NSL_, BC_) x 256.
// ---------------------------------------------------------------------------
__global__ void __launch_bounds__(256)
scatter_kernel() {
    __shared__ int sTot[C_];
    __shared__ int sPre[C_];
    __shared__ int sStart[C_];
    __shared__ int offs[C_];
    int blk = blockIdx.x;
    int bc  = blockIdx.y;
    int t   = threadIdx.x;

    if (t < C_) {
        const int* ph = g_parthist + bc * NSL_ * C_ + t;
        int pre = 0, tot = 0;
#pragma unroll
        for (int s = 0; s < NSL_; s++) {
            int v = __ldg(ph + s * C_);
            if (s < blk) pre += v;
            tot += v;
        }
        sPre[t] = pre;
        sTot[t] = tot;
    }
    __syncthreads();

    if (t < 32) {
        int base = t * 5;
        int v[5], s = 0;
#pragma unroll
        for (int i = 0; i < 5; i++) {
            int c = base + i;
            v[i] = (c < C_) ? sTot[c] : 0;
            s += v[i];
        }
        int run = s;
#pragma unroll
        for (int o = 1; o < 32; o <<= 1) {
            int x = __shfl_up_sync(0xFFFFFFFFu, run, o);
            if (t >= o) run += x;
        }
        int acc = run - s;
#pragma unroll
        for (int i = 0; i < 5; i++) {
            int c = base + i;
            if (c < C_) {
                sStart[c] = acc;
                if (blk == 0) g_starts[bc * (C_ + 1) + c] = acc;
            }
            acc += v[i];
        }
        if (t == 31 && blk == 0) g_starts[bc * (C_ + 1) + C_] = N_;
    }
    __syncthreads();

    if (t < C_) offs[t] = sStart[t] + sPre[t];
    __syncthreads();

    int base = bc * N_ + blk * SL_;
#pragma unroll
    for (int r = 0; r < 2; r++) {
        int i = r * 256 + t;
        int lab = g_lab[base + i];
        int p = atomicAdd(&offs[lab], 1);
        g_order[bc * N_ + p] = blk * SL_ + i;
    }
}

// ---------------------------------------------------------------------------
// Kernel 2: per-cluster centers. Warp owns a cluster; 8-member batches,
// ord prefetched one batch ahead. grid (32,16) x 256, 3 blocks/SM.
// ---------------------------------------------------------------------------
__global__ void __launch_bounds__(256, 3)
centers_kernel(const float* __restrict__ Q,
               const float* __restrict__ K,
               const float* __restrict__ V) {
    int b    = blockIdx.x;
    int bc   = b & 3;
    int wid  = threadIdx.x >> 5;
    int lane = threadIdx.x & 31;
    int half = lane >> 4;
    int dc   = lane & 15;

    const float4* Qb = (const float4*)(Q + (size_t)b * N_ * D_);
    const float4* Kb = (const float4*)(K + (size_t)b * N_ * D_);
    const float4* Vb = (const float4*)(V + (size_t)b * N_ * D_);
    const int* ord = g_order + bc * N_;
    const int* sts = g_starts + bc * (C_ + 1);

    for (int c = blockIdx.y * 8 + wid; c < C_; c += 128) {
        int s0 = sts[c], s1 = sts[c + 1];
        float w = (s1 > s0) ? 1.0f / (float)(s1 - s0) : 0.0f;
        float4 aq = {0.f,0.f,0.f,0.f}, ak = aq, av = aq;

        int   nn[4];
        float mk[4];
#pragma unroll
        for (int p = 0; p < 4; p++) {
            int mm = s0 + 2 * p + half;
            bool vld = mm < s1;
            nn[p] = __ldg(ord + (vld ? mm : 0));
            mk[p] = vld ? 1.0f : 0.0f;
        }
        for (int m = s0; m < s1; m += 8) {
            int   nn2[4];
            float mk2[4];
#pragma unroll
            for (int p = 0; p < 4; p++) {
                int mm = m + 8 + 2 * p + half;
                bool vld = mm < s1;
                nn2[p] = __ldg(ord + (vld ? mm : 0));
                mk2[p] = vld ? 1.0f : 0.0f;
            }
            float4 q4[4], k4[4], v4[4];
#pragma unroll
            for (int p = 0; p < 4; p++) {
                size_t off = (size_t)nn[p] * 16 + dc;
                q4[p] = Qb[off];
                k4[p] = Kb[off];
                v4[p] = Vb[off];
            }
#pragma unroll
            for (int p = 0; p < 4; p++) {
                aq.x = fmaf(mk[p], q4[p].x, aq.x); aq.y = fmaf(mk[p], q4[p].y, aq.y);
                aq.z = fmaf(mk[p], q4[p].z, aq.z); aq.w = fmaf(mk[p], q4[p].w, aq.w);
                ak.x = fmaf(mk[p], k4[p].x, ak.x); ak.y = fmaf(mk[p], k4[p].y, ak.y);
                ak.z = fmaf(mk[p], k4[p].z, ak.z); ak.w = fmaf(mk[p], k4[p].w, ak.w);
                av.x = fmaf(mk[p], v4[p].x, av.x); av.y = fmaf(mk[p], v4[p].y, av.y);
                av.z = fmaf(mk[p], v4[p].z, av.z); av.w = fmaf(mk[p], v4[p].w, av.w);
            }
#pragma unroll
            for (int p = 0; p < 4; p++) { nn[p] = nn2[p]; mk[p] = mk2[p]; }
        }
        unsigned fm = 0xFFFFFFFFu;
        aq.x += __shfl_xor_sync(fm, aq.x, 16); aq.y += __shfl_xor_sync(fm, aq.y, 16);
        aq.z += __shfl_xor_sync(fm, aq.z, 16); aq.w += __shfl_xor_sync(fm, aq.w, 16);
        ak.x += __shfl_xor_sync(fm, ak.x, 16); ak.y += __shfl_xor_sync(fm, ak.y, 16);
        ak.z += __shfl_xor_sync(fm, ak.z, 16); ak.w += __shfl_xor_sync(fm, ak.w, 16);
        av.x += __shfl_xor_sync(fm, av.x, 16); av.y += __shfl_xor_sync(fm, av.y, 16);
        av.z += __shfl_xor_sync(fm, av.z, 16); av.w += __shfl_xor_sync(fm, av.w, 16);
        if (half == 0) {
            size_t o = (size_t)(b * C_ + c) * 16 + dc;
            ((float4*)g_Qc)[o] = make_float4(aq.x*w, aq.y*w, aq.z*w, aq.w*w);
            ((float4*)g_Kc)[o] = make_float4(ak.x*w, ak.y*w, ak.z*w, ak.w*w);
            ((float4*)g_Vc)[o] = make_float4(av.x*w, av.y*w, av.z*w, av.w*w);
        }
    }
}

// ---------------------------------------------------------------------------
// Kernel 3a: scores + softmax -> g_P. grid (32, 9) x 256, 2 blocks/SM.
// SMEM (floats): sK[C*68] | sQt[16*68] | sP[16*132] | sCnt[132]  ~48.4KB
// ---------------------------------------------------------------------------
#define SC_SMEM_FLOATS (C_*68 + 16*68 + 16*132 + 132)
#define SC_SMEM_BYTES  (SC_SMEM_FLOATS * 4)

__global__ void __launch_bounds__(256, 2)
scores_kernel(float* __restrict__ attn_out) {
    extern __shared__ __align__(16) float smem[];
    float* sK   = smem;                    // stride 68 (17 f4)
    float* sQt  = sK + C_ * 68;            // stride 68
    float* sP   = sQt + 16 * 68;           // 16 x 132
    float* sCnt = sP + 16 * 132;

    int b  = blockIdx.x;
    int bc = b & 3;
    int q0 = blockIdx.y * 16;
    int t  = threadIdx.x;

    const int* sts = g_starts + bc * (C_ + 1);
    for (int k = t; k < C_; k += 256) sCnt[k] = (float)(sts[k + 1] - sts[k]);

    float4* sK4 = (float4*)sK;
    float4* sQ4 = (float4*)sQt;
    const float4* Kc4 = (const float4*)(g_Kc + (size_t)b * C_ * D_);
    const float4* Qc4 = (const float4*)(g_Qc + (size_t)b * C_ * D_);
    for (int i = t; i < C_ * 16; i += 256) {
        int k = i >> 4, d4 = i & 15;
        sK4[k * 17 + d4] = Kc4[i];
    }
    {
        int j = t >> 4, d4 = t & 15, q = q0 + j;
        sQ4[j * 17 + d4] = (q < C_) ? Qc4[q * 16 + d4] : make_float4(0,0,0,0);
    }
    __syncthreads();

    // ---- Phase A: scores. thread = (q-quad jp4, k-slot). 4-way q blocking.
    {
        int w      = t >> 5;
        int jp4    = w >> 1;
        int kstart = (t & 31) + 32 * (w & 1);
        float4 a0[4], a1[4];
#pragma unroll
        for (int qi = 0; qi < 4; qi++) { a0[qi] = make_float4(0,0,0,0); a1[qi] = a0[qi]; }
#pragma unroll 4
        for (int d4 = 0; d4 < 16; d4++) {
            float4 kva = sK4[kstart * 17 + d4];
            float4 kvb = sK4[(kstart + 64) * 17 + d4];
#pragma unroll
            for (int qi = 0; qi < 4; qi++) {
                float4 qv = sQ4[(4 * jp4 + qi) * 17 + d4];
                a0[qi].x = fmaf(qv.x, kva.x, a0[qi].x); a0[qi].y = fmaf(qv.y, kva.y, a0[qi].y);
                a0[qi].z = fmaf(qv.z, kva.z, a0[qi].z); a0[qi].w = fmaf(qv.w, kva.w, a0[qi].w);
                a1[qi].x = fmaf(qv.x, kvb.x, a1[qi].x); a1[qi].y = fmaf(qv.y, kvb.y, a1[qi].y);
                a1[qi].z = fmaf(qv.z, kvb.z, a1[qi].z); a1[qi].w = fmaf(qv.w, kvb.w, a1[qi].w);
            }
        }
#pragma unroll
        for (int qi = 0; qi < 4; qi++) {
            sP[(4 * jp4 + qi) * 132 + kstart]      = (a0[qi].x + a0[qi].y) + (a0[qi].z + a0[qi].w);
            sP[(4 * jp4 + qi) * 132 + kstart + 64] = (a1[qi].x + a1[qi].y) + (a1[qi].z + a1[qi].w);
        }
        if (kstart == 0) {   // epilogue column k=128
            float4 a4[4];
#pragma unroll
            for (int qi = 0; qi < 4; qi++) a4[qi] = make_float4(0,0,0,0);
#pragma unroll 4
            for (int d4 = 0; d4 < 16; d4++) {
                float4 kv = sK4[128 * 17 + d4];
#pragma unroll
                for (int qi = 0; qi < 4; qi++) {
                    float4 qv = sQ4[(4 * jp4 + qi) * 17 + d4];
                    a4[qi].x = fmaf(qv.x, kv.x, a4[qi].x); a4[qi].y = fmaf(qv.y, kv.y, a4[qi].y);
                    a4[qi].z = fmaf(qv.z, kv.z, a4[qi].z); a4[qi].w = fmaf(qv.w, kv.w, a4[qi].w);
                }
            }
#pragma unroll
            for (int qi = 0; qi < 4; qi++)
                sP[(4 * jp4 + qi) * 132 + 128] = (a4[qi].x + a4[qi].y) + (a4[qi].z + a4[qi].w);
        }
    }
    __syncthreads();

    // ---- Softmax with count reweighting: one warp per q row.
    {
        int wid = t >> 5, lane = t & 31;
        for (int j = wid; j < 16; j += 8) {
            float* row = &sP[j * 132];
            float v[5];
            float mx = -1e30f;
#pragma unroll
            for (int i = 0; i < 5; i++) {
                int k = lane + 32 * i;
                v[i] = (k < C_) ? row[k] : -1e30f;
                mx = fmaxf(mx, v[i]);
            }
#pragma unroll
            for (int o = 16; o; o >>= 1) mx = fmaxf(mx, __shfl_xor_sync(0xFFFFFFFFu, mx, o));
            float e[5];
            float sum = 0.f;
#pragma unroll
            for (int i = 0; i < 5; i++) {
                int k = lane + 32 * i;
                e[i] = (k < C_) ? __expf(v[i] - mx) * sCnt[k] : 0.0f;
                sum += e[i];
            }
#pragma unroll
            for (int o = 16; o; o >>= 1) sum += __shfl_xor_sync(0xFFFFFFFFu, sum, o);
            float inv = 1.0f / sum;
#pragma unroll
            for (int i = 0; i < 5; i++) {
                int k = lane + 32 * i;
                if (k < 132) row[k] = (k < C_) ? e[i] * inv : 0.0f;   // zero-pad 129..131
            }
            if (lane == 0 && (q0 + j) < C_) attn_out[b * C_ + q0 + j] = e[0] * inv;
        }
    }
    __syncthreads();

    // ---- Write P tile to global (float4, contiguous 16x132 block)
    {
        float4* gP4 = (float4*)(g_P + (size_t)(b * NT_ + blockIdx.y) * 16 * 132);
        const float4* sP4 = (const float4*)sP;
        for (int i = t; i < 16 * 33; i += 256) gP4[i] = sP4[i];
    }
}

// ---------------------------------------------------------------------------
// Kernel 3b: Vout = P @ Vc. grid (32, 9) x 256, 3 blocks/SM.
// SMEM (floats): sV[C*64] | sP[16*132]  ~41.6KB
// ---------------------------------------------------------------------------
#define VO_SMEM_FLOATS (C_*64 + 16*132)
#define VO_SMEM_BYTES  (VO_SMEM_FLOATS * 4)

__global__ void __launch_bounds__(256, 3)
vout_kernel() {
    extern __shared__ __align__(16) float smem[];
    float* sV = smem;                      // stride 64 (16 f4)
    float* sP = sV + C_ * 64;              // 16 x 132

    int b  = blockIdx.x;
    int q0 = blockIdx.y * 16;
    int t  = threadIdx.x;

    float4* sV4 = (float4*)sV;
    const float4* Vc4 = (const float4*)(g_Vc + (size_t)b * C_ * D_);
    for (int i = t; i < C_ * 16; i += 256) sV4[i] = Vc4[i];
    {
        float4* sP4 = (float4*)sP;
        const float4* gP4 = (const float4*)(g_P + (size_t)(b * NT_ + blockIdx.y) * 16 * 132);
        for (int i = t; i < 16 * 33; i += 256) sP4[i] = gP4[i];
    }
    __syncthreads();

    int j  = t >> 4;
    int dv = t & 15;
    if (q0 + j >= C_) return;
    const float* pr = &sP[j * 132];
    float4 acc = make_float4(0, 0, 0, 0);
#pragma unroll 4
    for (int k = 0; k < C_; k++) {
        float4 v = sV4[k * 16 + dv];
        float  p = pr[k];
        acc.x = fmaf(p, v.x, acc.x); acc.y = fmaf(p, v.y, acc.y);
        acc.z = fmaf(p, v.z, acc.z); acc.w = fmaf(p, v.w, acc.w);
    }
    ((float4*)g_Vout)[(size_t)(b * C_ + q0 + j) * 16 + dv] = acc;
}

// ---------------------------------------------------------------------------
// Kernel 4: gather broadcast out[b,n,:] = Vout[b, g_lab[b%4, n], :].
// grid 8192 x 256 — saturates store issue chip-wide; Vout is L2-resident.
// ---------------------------------------------------------------------------
__global__ void __launch_bounds__(256)
gather_kernel(float* __restrict__ out) {
    int idx = blockIdx.x * 256 + threadIdx.x;   // over B*N*(D/4) float4s
    int dv  = idx & 15;
    int n   = (idx >> 4) & (N_ - 1);
    int b   = idx >> 16;
    int bc  = b & 3;
    int c   = __ldg(g_lab + bc * N_ + n);
    float4 v = ((const float4*)g_Vout)[(b * C_ + c) * 16 + dv];
    ((float4*)out)[idx] = v;
}

// ---------------------------------------------------------------------------
extern "C" void kernel_launch(void* const* d_in, const int* in_sizes, int n_in,
                              void* d_out, int out_size) {
    const float* Q  = (const float*)d_in[0];
    const float* K  = (const float*)d_in[1];
    const float* V  = (const float*)d_in[2];
    const void*  cl = d_in[3];
    float* out = (float*)d_out;
    float* attn_out = out + (size_t)B_ * N_ * D_;

    cudaFuncSetAttribute(scores_kernel, cudaFuncAttributeMaxDynamicSharedMemorySize,
                         SC_SMEM_BYTES);
    cudaFuncSetAttribute(vout_kernel, cudaFuncAttributeMaxDynamicSharedMemorySize,
                         VO_SMEM_BYTES);

    hist_kernel<<<dim3(NSL_, BC_), 256>>>(cl);
    scatter_kernel<<<dim3(NSL_, BC_), 256>>>();
    centers_kernel<<<dim3(B_, 16), 256>>>(Q, K, V);
    scores_kernel<<<dim3(B_, NT_), 256, SC_SMEM_BYTES>>>(attn_out);
    vout_kernel<<<dim3(B_, NT_), 256, VO_SMEM_BYTES>>>();
    gather_kernel<<<(B_ * N_ * (D_ / 4)) / 256, 256>>>(out);
}

// round 16
// speedup vs baseline: 1.3236x; 1.1045x over previous
#include <cuda_runtime.h>
#include <cuda_bf16.h>

#define B_   32
#define N_   4096
#define D_   64
#define BC_  4
#define C_   129
#define NSL_ 8                 // slices per cluster-batch
#define SL_  (N_ / NSL_)       // 512 labels per slice
#define NT_  9                 // q tiles of 16

// Scratch (no allocations allowed)
__device__ __align__(16) int g_lab[BC_ * N_];
__device__ __align__(16) int g_parthist[BC_ * NSL_ * C_];
__device__ __align__(16) int g_order[BC_ * N_];
__device__ __align__(16) int g_starts[BC_ * (C_ + 1)];
__device__ __align__(16) float g_Qc[B_ * C_ * D_];
__device__ __align__(16) float g_Kc[B_ * C_ * D_];
__device__ __align__(16) float g_Vc[B_ * C_ * D_];
__device__ __align__(16) float g_Vout[B_ * C_ * D_];       // attended centers

// ---------------------------------------------------------------------------
// Kernel 1a: decode labels + per-slice histogram. grid (NSL_, BC_) x 256.
// ---------------------------------------------------------------------------
__global__ void __launch_bounds__(256)
hist_kernel(const void* __restrict__ cl_raw) {
    __shared__ int hist[C_];
    __shared__ int s_bad;
    int blk = blockIdx.x;
    int bc  = blockIdx.y;
    int t   = threadIdx.x;

    if (t < 32) {
        long long v = __ldg((const long long*)cl_raw + t);
        unsigned bad = __ballot_sync(0xFFFFFFFFu, v < 0 || v >= C_);
        if (t == 0) s_bad = (bad != 0);
    }
    if (t < C_) hist[t] = 0;
    __syncthreads();

    int base = bc * N_ + blk * SL_;
    int lab[2];
    if (s_bad) {
        const int* c32 = (const int*)cl_raw;
        lab[0] = c32[base + t];
        lab[1] = c32[base + t + 256];
    } else {
        const long long* c64 = (const long long*)cl_raw;
        lab[0] = (int)c64[base + t];
        lab[1] = (int)c64[base + t + 256];
    }
    g_lab[base + t]       = lab[0];
    g_lab[base + t + 256] = lab[1];
    atomicAdd(&hist[lab[0]], 1);
    atomicAdd(&hist[lab[1]], 1);
    __syncthreads();

    if (t < C_) g_parthist[(bc * NSL_ + blk) * C_ + t] = hist[t];
}

// ---------------------------------------------------------------------------
// Kernel 1b: combine partial hists, scan, scatter own slice.
// grid (NSL_, BC_) x 256.
// ---------------------------------------------------------------------------
__global__ void __launch_bounds__(256)
scatter_kernel() {
    __shared__ int sTot[C_];
    __shared__ int sPre[C_];
    __shared__ int sStart[C_];
    __shared__ int offs[C_];
    int blk = blockIdx.x;
    int bc  = blockIdx.y;
    int t   = threadIdx.x;

    if (t < C_) {
        const int* ph = g_parthist + bc * NSL_ * C_ + t;
        int pre = 0, tot = 0;
#pragma unroll
        for (int s = 0; s < NSL_; s++) {
            int v = __ldg(ph + s * C_);
            if (s < blk) pre += v;
            tot += v;
        }
        sPre[t] = pre;
        sTot[t] = tot;
    }
    __syncthreads();

    if (t < 32) {
        int base = t * 5;
        int v[5], s = 0;
#pragma unroll
        for (int i = 0; i < 5; i++) {
            int c = base + i;
            v[i] = (c < C_) ? sTot[c] : 0;
            s += v[i];
        }
        int run = s;
#pragma unroll
        for (int o = 1; o < 32; o <<= 1) {
            int x = __shfl_up_sync(0xFFFFFFFFu, run, o);
            if (t >= o) run += x;
        }
        int acc = run - s;
#pragma unroll
        for (int i = 0; i < 5; i++) {
            int c = base + i;
            if (c < C_) {
                sStart[c] = acc;
                if (blk == 0) g_starts[bc * (C_ + 1) + c] = acc;
            }
            acc += v[i];
        }
        if (t == 31 && blk == 0) g_starts[bc * (C_ + 1) + C_] = N_;
    }
    __syncthreads();

    if (t < C_) offs[t] = sStart[t] + sPre[t];
    __syncthreads();

    int base = bc * N_ + blk * SL_;
#pragma unroll
    for (int r = 0; r < 2; r++) {
        int i = r * 256 + t;
        int lab = g_lab[base + i];
        int p = atomicAdd(&offs[lab], 1);
        g_order[bc * N_ + p] = blk * SL_ + i;
    }
}

// ---------------------------------------------------------------------------
// Kernel 2: per-cluster centers. Warp owns exactly one cluster (grid (32,17),
// c = y*8+wid, guard c<129 -> no double-work straggler warp). 8-member
// batches, ord prefetched one batch ahead. 3 blocks/SM.
// ---------------------------------------------------------------------------
__global__ void __launch_bounds__(256, 3)
centers_kernel(const float* __restrict__ Q,
               const float* __restrict__ K,
               const float* __restrict__ V) {
    int b    = blockIdx.x;
    int bc   = b & 3;
    int wid  = threadIdx.x >> 5;
    int lane = threadIdx.x & 31;
    int half = lane >> 4;
    int dc   = lane & 15;

    int c = blockIdx.y * 8 + wid;
    if (c >= C_) return;

    const float4* Qb = (const float4*)(Q + (size_t)b * N_ * D_);
    const float4* Kb = (const float4*)(K + (size_t)b * N_ * D_);
    const float4* Vb = (const float4*)(V + (size_t)b * N_ * D_);
    const int* ord = g_order + bc * N_;
    const int* sts = g_starts + bc * (C_ + 1);

    int s0 = sts[c], s1 = sts[c + 1];
    float w = (s1 > s0) ? 1.0f / (float)(s1 - s0) : 0.0f;
    float4 aq = {0.f,0.f,0.f,0.f}, ak = aq, av = aq;

    int   nn[4];
    float mk[4];
#pragma unroll
    for (int p = 0; p < 4; p++) {
        int mm = s0 + 2 * p + half;
        bool vld = mm < s1;
        nn[p] = __ldg(ord + (vld ? mm : 0));
        mk[p] = vld ? 1.0f : 0.0f;
    }
    for (int m = s0; m < s1; m += 8) {
        int   nn2[4];
        float mk2[4];
#pragma unroll
        for (int p = 0; p < 4; p++) {
            int mm = m + 8 + 2 * p + half;
            bool vld = mm < s1;
            nn2[p] = __ldg(ord + (vld ? mm : 0));
            mk2[p] = vld ? 1.0f : 0.0f;
        }
        float4 q4[4], k4[4], v4[4];
#pragma unroll
        for (int p = 0; p < 4; p++) {
            size_t off = (size_t)nn[p] * 16 + dc;
            q4[p] = Qb[off];
            k4[p] = Kb[off];
            v4[p] = Vb[off];
        }
#pragma unroll
        for (int p = 0; p < 4; p++) {
            aq.x = fmaf(mk[p], q4[p].x, aq.x); aq.y = fmaf(mk[p], q4[p].y, aq.y);
            aq.z = fmaf(mk[p], q4[p].z, aq.z); aq.w = fmaf(mk[p], q4[p].w, aq.w);
            ak.x = fmaf(mk[p], k4[p].x, ak.x); ak.y = fmaf(mk[p], k4[p].y, ak.y);
            ak.z = fmaf(mk[p], k4[p].z, ak.z); ak.w = fmaf(mk[p], k4[p].w, ak.w);
            av.x = fmaf(mk[p], v4[p].x, av.x); av.y = fmaf(mk[p], v4[p].y, av.y);
            av.z = fmaf(mk[p], v4[p].z, av.z); av.w = fmaf(mk[p], v4[p].w, av.w);
        }
#pragma unroll
        for (int p = 0; p < 4; p++) { nn[p] = nn2[p]; mk[p] = mk2[p]; }
    }
    unsigned fm = 0xFFFFFFFFu;
    aq.x += __shfl_xor_sync(fm, aq.x, 16); aq.y += __shfl_xor_sync(fm, aq.y, 16);
    aq.z += __shfl_xor_sync(fm, aq.z, 16); aq.w += __shfl_xor_sync(fm, aq.w, 16);
    ak.x += __shfl_xor_sync(fm, ak.x, 16); ak.y += __shfl_xor_sync(fm, ak.y, 16);
    ak.z += __shfl_xor_sync(fm, ak.z, 16); ak.w += __shfl_xor_sync(fm, ak.w, 16);
    av.x += __shfl_xor_sync(fm, av.x, 16); av.y += __shfl_xor_sync(fm, av.y, 16);
    av.z += __shfl_xor_sync(fm, av.z, 16); av.w += __shfl_xor_sync(fm, av.w, 16);
    if (half == 0) {
        size_t o = (size_t)(b * C_ + c) * 16 + dc;
        ((float4*)g_Qc)[o] = make_float4(aq.x*w, aq.y*w, aq.z*w, aq.w*w);
        ((float4*)g_Kc)[o] = make_float4(ak.x*w, ak.y*w, ak.z*w, ak.w*w);
        ((float4*)g_Vc)[o] = make_float4(av.x*w, av.y*w, av.z*w, av.w*w);
    }
}

// ---------------------------------------------------------------------------
// Kernel 3: scores + softmax + P@V -> g_Vout. grid (32, 9) x 256, 2 blocks/SM.
// SMEM (floats): sK[C*68] | sV[C*64] | sQt[16*68] | sP[16*132] | sCnt[132]
// = 81.4KB. P never leaves SMEM.
// ---------------------------------------------------------------------------
#define SC_SMEM_FLOATS (C_*68 + C_*64 + 16*68 + 16*132 + 132)
#define SC_SMEM_BYTES  (SC_SMEM_FLOATS * 4)

__global__ void __launch_bounds__(256, 2)
scores_kernel(float* __restrict__ attn_out) {
    extern __shared__ __align__(16) float smem[];
    float* sK   = smem;                    // stride 68 (17 f4)
    float* sV   = sK + C_ * 68;            // stride 64 (16 f4)
    float* sQt  = sV + C_ * 64;            // stride 68
    float* sP   = sQt + 16 * 68;           // 16 x 132
    float* sCnt = sP + 16 * 132;

    int b  = blockIdx.x;
    int bc = b & 3;
    int q0 = blockIdx.y * 16;
    int t  = threadIdx.x;

    const int* sts = g_starts + bc * (C_ + 1);
    for (int k = t; k < C_; k += 256) sCnt[k] = (float)(sts[k + 1] - sts[k]);

    float4* sK4 = (float4*)sK;
    float4* sV4 = (float4*)sV;
    float4* sQ4 = (float4*)sQt;
    const float4* Kc4 = (const float4*)(g_Kc + (size_t)b * C_ * D_);
    const float4* Vc4 = (const float4*)(g_Vc + (size_t)b * C_ * D_);
    const float4* Qc4 = (const float4*)(g_Qc + (size_t)b * C_ * D_);
    for (int i = t; i < C_ * 16; i += 256) {
        int k = i >> 4, d4 = i & 15;
        sK4[k * 17 + d4] = Kc4[i];
        sV4[i] = Vc4[i];
    }
    {
        int j = t >> 4, d4 = t & 15, q = q0 + j;
        sQ4[j * 17 + d4] = (q < C_) ? Qc4[q * 16 + d4] : make_float4(0,0,0,0);
    }
    __syncthreads();

    // ---- Phase A: scores. thread = (q-quad jp4, k-slot). 4-way q blocking.
    {
        int w      = t >> 5;
        int jp4    = w >> 1;
        int kstart = (t & 31) + 32 * (w & 1);
        float4 a0[4], a1[4];
#pragma unroll
        for (int qi = 0; qi < 4; qi++) { a0[qi] = make_float4(0,0,0,0); a1[qi] = a0[qi]; }
#pragma unroll 4
        for (int d4 = 0; d4 < 16; d4++) {
            float4 kva = sK4[kstart * 17 + d4];
            float4 kvb = sK4[(kstart + 64) * 17 + d4];
#pragma unroll
            for (int qi = 0; qi < 4; qi++) {
                float4 qv = sQ4[(4 * jp4 + qi) * 17 + d4];
                a0[qi].x = fmaf(qv.x, kva.x, a0[qi].x); a0[qi].y = fmaf(qv.y, kva.y, a0[qi].y);
                a0[qi].z = fmaf(qv.z, kva.z, a0[qi].z); a0[qi].w = fmaf(qv.w, kva.w, a0[qi].w);
                a1[qi].x = fmaf(qv.x, kvb.x, a1[qi].x); a1[qi].y = fmaf(qv.y, kvb.y, a1[qi].y);
                a1[qi].z = fmaf(qv.z, kvb.z, a1[qi].z); a1[qi].w = fmaf(qv.w, kvb.w, a1[qi].w);
            }
        }
#pragma unroll
        for (int qi = 0; qi < 4; qi++) {
            sP[(4 * jp4 + qi) * 132 + kstart]      = (a0[qi].x + a0[qi].y) + (a0[qi].z + a0[qi].w);
            sP[(4 * jp4 + qi) * 132 + kstart + 64] = (a1[qi].x + a1[qi].y) + (a1[qi].z + a1[qi].w);
        }
        if (kstart == 0) {   // epilogue column k=128
            float4 a4[4];
#pragma unroll
            for (int qi = 0; qi < 4; qi++) a4[qi] = make_float4(0,0,0,0);
#pragma unroll 4
            for (int d4 = 0; d4 < 16; d4++) {
                float4 kv = sK4[128 * 17 + d4];
#pragma unroll
                for (int qi = 0; qi < 4; qi++) {
                    float4 qv = sQ4[(4 * jp4 + qi) * 17 + d4];
                    a4[qi].x = fmaf(qv.x, kv.x, a4[qi].x); a4[qi].y = fmaf(qv.y, kv.y, a4[qi].y);
                    a4[qi].z = fmaf(qv.z, kv.z, a4[qi].z); a4[qi].w = fmaf(qv.w, kv.w, a4[qi].w);
                }
            }
#pragma unroll
            for (int qi = 0; qi < 4; qi++)
                sP[(4 * jp4 + qi) * 132 + 128] = (a4[qi].x + a4[qi].y) + (a4[qi].z + a4[qi].w);
        }
    }
    __syncthreads();

    // ---- Softmax with count reweighting: one warp per q row.
    {
        int wid = t >> 5, lane = t & 31;
        for (int j = wid; j < 16; j += 8) {
            float* row = &sP[j * 132];
            float v[5];
            float mx = -1e30f;
#pragma unroll
            for (int i = 0; i < 5; i++) {
                int k = lane + 32 * i;
                v[i] = (k < C_) ? row[k] : -1e30f;
                mx = fmaxf(mx, v[i]);
            }
#pragma unroll
            for (int o = 16; o; o >>= 1) mx = fmaxf(mx, __shfl_xor_sync(0xFFFFFFFFu, mx, o));
            float e[5];
            float sum = 0.f;
#pragma unroll
            for (int i = 0; i < 5; i++) {
                int k = lane + 32 * i;
                e[i] = (k < C_) ? __expf(v[i] - mx) * sCnt[k] : 0.0f;
                sum += e[i];
            }
#pragma unroll
            for (int o = 16; o; o >>= 1) sum += __shfl_xor_sync(0xFFFFFFFFu, sum, o);
            float inv = 1.0f / sum;
#pragma unroll
            for (int i = 0; i < 5; i++) {
                int k = lane + 32 * i;
                if (k < 132) row[k] = (k < C_) ? e[i] * inv : 0.0f;
            }
            if (lane == 0 && (q0 + j) < C_) attn_out[b * C_ + q0 + j] = e[0] * inv;
        }
    }
    __syncthreads();

    // ---- Phase B: Vout[j][dv] = sum_k P[j][k] * V[k][dv] (P in SMEM).
    {
        int j  = t >> 4;
        int dv = t & 15;
        if (q0 + j < C_) {
            const float* pr = &sP[j * 132];
            float4 acc = make_float4(0, 0, 0, 0);
#pragma unroll 4
            for (int k = 0; k < C_; k++) {
                float4 v = sV4[k * 16 + dv];
                float  p = pr[k];
                acc.x = fmaf(p, v.x, acc.x); acc.y = fmaf(p, v.y, acc.y);
                acc.z = fmaf(p, v.z, acc.z); acc.w = fmaf(p, v.w, acc.w);
            }
            ((float4*)g_Vout)[(size_t)(b * C_ + q0 + j) * 16 + dv] = acc;
        }
    }
}

// ---------------------------------------------------------------------------
// Kernel 4: gather broadcast out[b,n,:] = Vout[b, g_lab[b%4, n], :].
// grid 8192 x 256 — saturates store issue chip-wide; Vout is L2-resident.
// ---------------------------------------------------------------------------
__global__ void __launch_bounds__(256)
gather_kernel(float* __restrict__ out) {
    int idx = blockIdx.x * 256 + threadIdx.x;   // over B*N*(D/4) float4s
    int dv  = idx & 15;
    int n   = (idx >> 4) & (N_ - 1);
    int b   = idx >> 16;
    int bc  = b & 3;
    int c   = __ldg(g_lab + bc * N_ + n);
    float4 v = ((const float4*)g_Vout)[(b * C_ + c) * 16 + dv];
    ((float4*)out)[idx] = v;
}

// ---------------------------------------------------------------------------
extern "C" void kernel_launch(void* const* d_in, const int* in_sizes, int n_in,
                              void* d_out, int out_size) {
    const float* Q  = (const float*)d_in[0];
    const float* K  = (const float*)d_in[1];
    const float* V  = (const float*)d_in[2];
    const void*  cl = d_in[3];
    float* out = (float*)d_out;
    float* attn_out = out + (size_t)B_ * N_ * D_;

    cudaFuncSetAttribute(scores_kernel, cudaFuncAttributeMaxDynamicSharedMemorySize,
                         SC_SMEM_BYTES);

    hist_kernel<<<dim3(NSL_, BC_), 256>>>(cl);
    scatter_kernel<<<dim3(NSL_, BC_), 256>>>();
    centers_kernel<<<dim3(B_, 17), 256>>>(Q, K, V);
    scores_kernel<<<dim3(B_, NT_), 256, SC_SMEM_BYTES>>>(attn_out);
    gather_kernel<<<(B_ * N_ * (D_ / 4)) / 256, 256>>>(out);
}

// round 17
// speedup vs baseline: 1.3244x; 1.0006x over previous
#include <cuda_runtime.h>
#include <cuda_bf16.h>

#define B_   32
#define N_   4096
#define D_   64
#define BC_  4
#define C_   129
#define NSL_ 8                 // slices per cluster-batch
#define SL_  (N_ / NSL_)       // 512 labels per slice
#define NT_  9                 // q tiles of 16

// Scratch (no allocations allowed)
__device__ __align__(16) int g_lab[BC_ * N_];
__device__ __align__(16) int g_parthist[BC_ * NSL_ * C_];
__device__ __align__(16) int g_order[BC_ * N_];
__device__ __align__(16) int g_starts[BC_ * (C_ + 1)];
__device__ __align__(16) float g_Qc[B_ * C_ * D_];
__device__ __align__(16) float g_Kc[B_ * C_ * D_];
__device__ __align__(16) float g_Vc[B_ * C_ * D_];
__device__ __align__(16) float g_Vout[B_ * C_ * D_];       // attended centers

// ---------------------------------------------------------------------------
// Kernel 1a: decode labels + per-slice histogram. grid (NSL_, BC_) x 256.
// ---------------------------------------------------------------------------
__global__ void __launch_bounds__(256)
hist_kernel(const void* __restrict__ cl_raw) {
    __shared__ int hist[C_];
    __shared__ int s_bad;
    int blk = blockIdx.x;
    int bc  = blockIdx.y;
    int t   = threadIdx.x;

    if (t < 32) {
        long long v = __ldg((const long long*)cl_raw + t);
        unsigned bad = __ballot_sync(0xFFFFFFFFu, v < 0 || v >= C_);
        if (t == 0) s_bad = (bad != 0);
    }
    if (t < C_) hist[t] = 0;
    __syncthreads();

    int base = bc * N_ + blk * SL_;
    int lab[2];
    if (s_bad) {
        const int* c32 = (const int*)cl_raw;
        lab[0] = c32[base + t];
        lab[1] = c32[base + t + 256];
    } else {
        const long long* c64 = (const long long*)cl_raw;
        lab[0] = (int)c64[base + t];
        lab[1] = (int)c64[base + t + 256];
    }
    g_lab[base + t]       = lab[0];
    g_lab[base + t + 256] = lab[1];
    atomicAdd(&hist[lab[0]], 1);
    atomicAdd(&hist[lab[1]], 1);
    __syncthreads();

    if (t < C_) g_parthist[(bc * NSL_ + blk) * C_ + t] = hist[t];
}

// ---------------------------------------------------------------------------
// Kernel 1b: combine partial hists, scan, scatter own slice.
// grid (NSL_, BC_) x 256.
// ---------------------------------------------------------------------------
__global__ void __launch_bounds__(256)
scatter_kernel() {
    __shared__ int sTot[C_];
    __shared__ int sPre[C_];
    __shared__ int sStart[C_];
    __shared__ int offs[C_];
    int blk = blockIdx.x;
    int bc  = blockIdx.y;
    int t   = threadIdx.x;

    if (t < C_) {
        const int* ph = g_parthist + bc * NSL_ * C_ + t;
        int pre = 0, tot = 0;
#pragma unroll
        for (int s = 0; s < NSL_; s++) {
            int v = __ldg(ph + s * C_);
            if (s < blk) pre += v;
            tot += v;
        }
        sPre[t] = pre;
        sTot[t] = tot;
    }
    __syncthreads();

    if (t < 32) {
        int base = t * 5;
        int v[5], s = 0;
#pragma unroll
        for (int i = 0; i < 5; i++) {
            int c = base + i;
            v[i] = (c < C_) ? sTot[c] : 0;
            s += v[i];
        }
        int run = s;
#pragma unroll
        for (int o = 1; o < 32; o <<= 1) {
            int x = __shfl_up_sync(0xFFFFFFFFu, run, o);
            if (t >= o) run += x;
        }
        int acc = run - s;
#pragma unroll
        for (int i = 0; i < 5; i++) {
            int c = base + i;
            if (c < C_) {
                sStart[c] = acc;
                if (blk == 0) g_starts[bc * (C_ + 1) + c] = acc;
            }
            acc += v[i];
        }
        if (t == 31 && blk == 0) g_starts[bc * (C_ + 1) + C_] = N_;
    }
    __syncthreads();

    if (t < C_) offs[t] = sStart[t] + sPre[t];
    __syncthreads();

    int base = bc * N_ + blk * SL_;
#pragma unroll
    for (int r = 0; r < 2; r++) {
        int i = r * 256 + t;
        int lab = g_lab[base + i];
        int p = atomicAdd(&offs[lab], 1);
        g_order[bc * N_ + p] = blk * SL_ + i;
    }
}

// ---------------------------------------------------------------------------
// Kernel 2: per-cluster centers. Warp owns exactly one cluster (grid (32,17)).
// 8-member batches, ord prefetched one batch ahead. 3 blocks/SM.
// ---------------------------------------------------------------------------
__global__ void __launch_bounds__(256, 3)
centers_kernel(const float* __restrict__ Q,
               const float* __restrict__ K,
               const float* __restrict__ V) {
    int b    = blockIdx.x;
    int bc   = b & 3;
    int wid  = threadIdx.x >> 5;
    int lane = threadIdx.x & 31;
    int half = lane >> 4;
    int dc   = lane & 15;

    int c = blockIdx.y * 8 + wid;
    if (c >= C_) return;

    const float4* Qb = (const float4*)(Q + (size_t)b * N_ * D_);
    const float4* Kb = (const float4*)(K + (size_t)b * N_ * D_);
    const float4* Vb = (const float4*)(V + (size_t)b * N_ * D_);
    const int* ord = g_order + bc * N_;
    const int* sts = g_starts + bc * (C_ + 1);

    int s0 = sts[c], s1 = sts[c + 1];
    float w = (s1 > s0) ? 1.0f / (float)(s1 - s0) : 0.0f;
    float4 aq = {0.f,0.f,0.f,0.f}, ak = aq, av = aq;

    int   nn[4];
    float mk[4];
#pragma unroll
    for (int p = 0; p < 4; p++) {
        int mm = s0 + 2 * p + half;
        bool vld = mm < s1;
        nn[p] = __ldg(ord + (vld ? mm : 0));
        mk[p] = vld ? 1.0f : 0.0f;
    }
    for (int m = s0; m < s1; m += 8) {
        int   nn2[4];
        float mk2[4];
#pragma unroll
        for (int p = 0; p < 4; p++) {
            int mm = m + 8 + 2 * p + half;
            bool vld = mm < s1;
            nn2[p] = __ldg(ord + (vld ? mm : 0));
            mk2[p] = vld ? 1.0f : 0.0f;
        }
        float4 q4[4], k4[4], v4[4];
#pragma unroll
        for (int p = 0; p < 4; p++) {
            size_t off = (size_t)nn[p] * 16 + dc;
            q4[p] = Qb[off];
            k4[p] = Kb[off];
            v4[p] = Vb[off];
        }
#pragma unroll
        for (int p = 0; p < 4; p++) {
            aq.x = fmaf(mk[p], q4[p].x, aq.x); aq.y = fmaf(mk[p], q4[p].y, aq.y);
            aq.z = fmaf(mk[p], q4[p].z, aq.z); aq.w = fmaf(mk[p], q4[p].w, aq.w);
            ak.x = fmaf(mk[p], k4[p].x, ak.x); ak.y = fmaf(mk[p], k4[p].y, ak.y);
            ak.z = fmaf(mk[p], k4[p].z, ak.z); ak.w = fmaf(mk[p], k4[p].w, ak.w);
            av.x = fmaf(mk[p], v4[p].x, av.x); av.y = fmaf(mk[p], v4[p].y, av.y);
            av.z = fmaf(mk[p], v4[p].z, av.z); av.w = fmaf(mk[p], v4[p].w, av.w);
        }
#pragma unroll
        for (int p = 0; p < 4; p++) { nn[p] = nn2[p]; mk[p] = mk2[p]; }
    }
    unsigned fm = 0xFFFFFFFFu;
    aq.x += __shfl_xor_sync(fm, aq.x, 16); aq.y += __shfl_xor_sync(fm, aq.y, 16);
    aq.z += __shfl_xor_sync(fm, aq.z, 16); aq.w += __shfl_xor_sync(fm, aq.w, 16);
    ak.x += __shfl_xor_sync(fm, ak.x, 16); ak.y += __shfl_xor_sync(fm, ak.y, 16);
    ak.z += __shfl_xor_sync(fm, ak.z, 16); ak.w += __shfl_xor_sync(fm, ak.w, 16);
    av.x += __shfl_xor_sync(fm, av.x, 16); av.y += __shfl_xor_sync(fm, av.y, 16);
    av.z += __shfl_xor_sync(fm, av.z, 16); av.w += __shfl_xor_sync(fm, av.w, 16);
    if (half == 0) {
        size_t o = (size_t)(b * C_ + c) * 16 + dc;
        ((float4*)g_Qc)[o] = make_float4(aq.x*w, aq.y*w, aq.z*w, aq.w*w);
        ((float4*)g_Kc)[o] = make_float4(ak.x*w, ak.y*w, ak.z*w, ak.w*w);
        ((float4*)g_Vc)[o] = make_float4(av.x*w, av.y*w, av.z*w, av.w*w);
    }
}

// ---------------------------------------------------------------------------
// Kernel 3: scores + softmax + P@V -> g_Vout. grid (32, 9) x 256, 2 blocks/SM.
// SMEM (floats): sK[C*68] | sV[C*64] | sQt[16*68] | sP[16*132] | sCnt[132]
// = 81.4KB. P never leaves SMEM.
// ---------------------------------------------------------------------------
#define SC_SMEM_FLOATS (C_*68 + C_*64 + 16*68 + 16*132 + 132)
#define SC_SMEM_BYTES  (SC_SMEM_FLOATS * 4)

__global__ void __launch_bounds__(256, 2)
scores_kernel(float* __restrict__ attn_out) {
    extern __shared__ __align__(16) float smem[];
    float* sK   = smem;                    // stride 68 (17 f4)
    float* sV   = sK + C_ * 68;            // stride 64 (16 f4)
    float* sQt  = sV + C_ * 64;            // stride 68
    float* sP   = sQt + 16 * 68;           // 16 x 132
    float* sCnt = sP + 16 * 132;

    int b  = blockIdx.x;
    int bc = b & 3;
    int q0 = blockIdx.y * 16;
    int t  = threadIdx.x;

    const int* sts = g_starts + bc * (C_ + 1);
    for (int k = t; k < C_; k += 256) sCnt[k] = (float)(sts[k + 1] - sts[k]);

    float4* sK4 = (float4*)sK;
    float4* sV4 = (float4*)sV;
    float4* sQ4 = (float4*)sQt;
    const float4* Kc4 = (const float4*)(g_Kc + (size_t)b * C_ * D_);
    const float4* Vc4 = (const float4*)(g_Vc + (size_t)b * C_ * D_);
    const float4* Qc4 = (const float4*)(g_Qc + (size_t)b * C_ * D_);
    for (int i = t; i < C_ * 16; i += 256) {
        int k = i >> 4, d4 = i & 15;
        sK4[k * 17 + d4] = Kc4[i];
        sV4[i] = Vc4[i];
    }
    {
        int j = t >> 4, d4 = t & 15, q = q0 + j;
        sQ4[j * 17 + d4] = (q < C_) ? Qc4[q * 16 + d4] : make_float4(0,0,0,0);
    }
    __syncthreads();

    // ---- Phase A: scores. thread = (q-quad jp4, k-slot). 4-way q blocking.
    {
        int w      = t >> 5;
        int jp4    = w >> 1;
        int kstart = (t & 31) + 32 * (w & 1);
        float4 a0[4], a1[4];
#pragma unroll
        for (int qi = 0; qi < 4; qi++) { a0[qi] = make_float4(0,0,0,0); a1[qi] = a0[qi]; }
#pragma unroll 4
        for (int d4 = 0; d4 < 16; d4++) {
            float4 kva = sK4[kstart * 17 + d4];
            float4 kvb = sK4[(kstart + 64) * 17 + d4];
#pragma unroll
            for (int qi = 0; qi < 4; qi++) {
                float4 qv = sQ4[(4 * jp4 + qi) * 17 + d4];
                a0[qi].x = fmaf(qv.x, kva.x, a0[qi].x); a0[qi].y = fmaf(qv.y, kva.y, a0[qi].y);
                a0[qi].z = fmaf(qv.z, kva.z, a0[qi].z); a0[qi].w = fmaf(qv.w, kva.w, a0[qi].w);
                a1[qi].x = fmaf(qv.x, kvb.x, a1[qi].x); a1[qi].y = fmaf(qv.y, kvb.y, a1[qi].y);
                a1[qi].z = fmaf(qv.z, kvb.z, a1[qi].z); a1[qi].w = fmaf(qv.w, kvb.w, a1[qi].w);
            }
        }
#pragma unroll
        for (int qi = 0; qi < 4; qi++) {
            sP[(4 * jp4 + qi) * 132 + kstart]      = (a0[qi].x + a0[qi].y) + (a0[qi].z + a0[qi].w);
            sP[(4 * jp4 + qi) * 132 + kstart + 64] = (a1[qi].x + a1[qi].y) + (a1[qi].z + a1[qi].w);
        }
        if (kstart == 0) {   // epilogue column k=128
            float4 a4[4];
#pragma unroll
            for (int qi = 0; qi < 4; qi++) a4[qi] = make_float4(0,0,0,0);
#pragma unroll 4
            for (int d4 = 0; d4 < 16; d4++) {
                float4 kv = sK4[128 * 17 + d4];
#pragma unroll
                for (int qi = 0; qi < 4; qi++) {
                    float4 qv = sQ4[(4 * jp4 + qi) * 17 + d4];
                    a4[qi].x = fmaf(qv.x, kv.x, a4[qi].x); a4[qi].y = fmaf(qv.y, kv.y, a4[qi].y);
                    a4[qi].z = fmaf(qv.z, kv.z, a4[qi].z); a4[qi].w = fmaf(qv.w, kv.w, a4[qi].w);
                }
            }
#pragma unroll
            for (int qi = 0; qi < 4; qi++)
                sP[(4 * jp4 + qi) * 132 + 128] = (a4[qi].x + a4[qi].y) + (a4[qi].z + a4[qi].w);
        }
    }
    __syncthreads();

    // ---- Softmax with count reweighting: one warp per q row.
    {
        int wid = t >> 5, lane = t & 31;
        for (int j = wid; j < 16; j += 8) {
            float* row = &sP[j * 132];
            float v[5];
            float mx = -1e30f;
#pragma unroll
            for (int i = 0; i < 5; i++) {
                int k = lane + 32 * i;
                v[i] = (k < C_) ? row[k] : -1e30f;
                mx = fmaxf(mx, v[i]);
            }
#pragma unroll
            for (int o = 16; o; o >>= 1) mx = fmaxf(mx, __shfl_xor_sync(0xFFFFFFFFu, mx, o));
            float e[5];
            float sum = 0.f;
#pragma unroll
            for (int i = 0; i < 5; i++) {
                int k = lane + 32 * i;
                e[i] = (k < C_) ? __expf(v[i] - mx) * sCnt[k] : 0.0f;
                sum += e[i];
            }
#pragma unroll
            for (int o = 16; o; o >>= 1) sum += __shfl_xor_sync(0xFFFFFFFFu, sum, o);
            float inv = 1.0f / sum;
#pragma unroll
            for (int i = 0; i < 5; i++) {
                int k = lane + 32 * i;
                if (k < 132) row[k] = (k < C_) ? e[i] * inv : 0.0f;
            }
            if (lane == 0 && (q0 + j) < C_) attn_out[b * C_ + q0 + j] = e[0] * inv;
        }
    }
    __syncthreads();

    // ---- Phase B: Vout[j][dv] = sum_k P[j][k] * V[k][dv] (P in SMEM).
    {
        int j  = t >> 4;
        int dv = t & 15;
        if (q0 + j < C_) {
            const float* pr = &sP[j * 132];
            float4 acc = make_float4(0, 0, 0, 0);
#pragma unroll 4
            for (int k = 0; k < C_; k++) {
                float4 v = sV4[k * 16 + dv];
                float  p = pr[k];
                acc.x = fmaf(p, v.x, acc.x); acc.y = fmaf(p, v.y, acc.y);
                acc.z = fmaf(p, v.z, acc.z); acc.w = fmaf(p, v.w, acc.w);
            }
            ((float4*)g_Vout)[(size_t)(b * C_ + q0 + j) * 16 + dv] = acc;
        }
    }
}

// ---------------------------------------------------------------------------
// Kernel 4: gather broadcast, 4 items per thread (ILP=4 on the dependent
// lab->Vout->store chain). Item g covers idx = g*QTR + gid; stores stay fully
// coalesced within each warp. grid 2048 x 256.
// ---------------------------------------------------------------------------
#define GITEMS 4
#define GTOT   (B_ * N_ * (D_ / 4))
#define GQTR   (GTOT / GITEMS)

__global__ void __launch_bounds__(256)
gather_kernel(float* __restrict__ out) {
    int gid = blockIdx.x * 256 + threadIdx.x;

    int idx[GITEMS], c[GITEMS];
#pragma unroll
    for (int g = 0; g < GITEMS; g++) {
        idx[g] = g * GQTR + gid;
        int n  = (idx[g] >> 4) & (N_ - 1);
        int b  = idx[g] >> 16;
        c[g] = __ldg(g_lab + (b & 3) * N_ + n);
    }
    float4 v[GITEMS];
#pragma unroll
    for (int g = 0; g < GITEMS; g++) {
        int b  = idx[g] >> 16;
        int dv = idx[g] & 15;
        v[g] = ((const float4*)g_Vout)[(b * C_ + c[g]) * 16 + dv];
    }
#pragma unroll
    for (int g = 0; g < GITEMS; g++) {
        ((float4*)out)[idx[g]] = v[g];
    }
}

// ---------------------------------------------------------------------------
extern "C" void kernel_launch(void* const* d_in, const int* in_sizes, int n_in,
                              void* d_out, int out_size) {
    const float* Q  = (const float*)d_in[0];
    const float* K  = (const float*)d_in[1];
    const float* V  = (const float*)d_in[2];
    const void*  cl = d_in[3];
    float* out = (float*)d_out;
    float* attn_out = out + (size_t)B_ * N_ * D_;

    cudaFuncSetAttribute(scores_kernel, cudaFuncAttributeMaxDynamicSharedMemorySize,
                         SC_SMEM_BYTES);

    hist_kernel<<<dim3(NSL_, BC_), 256>>>(cl);
    scatter_kernel<<<dim3(NSL_, BC_), 256>>>();
    centers_kernel<<<dim3(B_, 17), 256>>>(Q, K, V);
    scores_kernel<<<dim3(B_, NT_), 256, SC_SMEM_BYTES>>>(attn_out);
    gather_kernel<<<GQTR / 256, 256>>>(out);
}